// round 1
// baseline (speedup 1.0000x reference)
#include <cuda_runtime.h>

#define BSZ   8
#define NMAX  64
#define NA    33600
#define BA    (BSZ * NA)          // 268800
#define NPRO_ 31
#define NALP_ 24
#define NADS_ 37

// ---------------- scratch (device globals; no allocation) ----------------
__device__ int   g_cnt[BA];
__device__ int   g_first[BA];
__device__ int   g_tgt[BA];
__device__ int   g_fgb[BA];
__device__ float g_iou[BA];
__device__ int   g_cls[8 * BA];   // j*BA + a : j=0 pro, 1 alp, 2..7 ads

// ---------------- init ----------------
__global__ void k_init() {
    int i = blockIdx.x * blockDim.x + threadIdx.x;
    if (i < BA) { g_cnt[i] = 0; g_first[i] = 0x7fffffff; }
}

// pairwise IoU exactly as reference _pairwise_iou (union clamp 1e-6)
__device__ __forceinline__ float pair_iou(float gx1, float gy1, float gx2, float gy2,
                                          float4 ab) {
    float ga  = __fmul_rn(__fsub_rn(gx2, gx1), __fsub_rn(gy2, gy1));
    float aa  = __fmul_rn(__fsub_rn(ab.z, ab.x), __fsub_rn(ab.w, ab.y));
    float iw  = fmaxf(__fsub_rn(fminf(gx2, ab.z), fmaxf(gx1, ab.x)), 0.f);
    float ih  = fmaxf(__fsub_rn(fminf(gy2, ab.w), fmaxf(gy1, ab.y)), 0.f);
    float ovl = __fmul_rn(iw, ih);
    float uni = fmaxf(__fsub_rn(__fadd_rn(ga, aa), ovl), 1e-6f);
    return __fdiv_rn(ovl, uni);
}

// ---------------- per-GT: top-9/level candidates, threshold, positives ----
__global__ void __launch_bounds__(96) k_assign(const float* __restrict__ anc,
                                               const float* __restrict__ gtb,
                                               const float* __restrict__ mask_gt) {
    int bg = blockIdx.x;                 // b*64 + g
    if (mask_gt[bg] <= 0.f) return;
    int b = bg >> 6;
    int g = bg & 63;

    const float* gt = gtb + bg * 4;
    float gx1 = gt[0], gy1 = gt[1], gx2 = gt[2], gy2 = gt[3];
    float gcx = __fmul_rn(__fadd_rn(gx1, gx2), 0.5f);
    float gcy = __fmul_rn(__fadd_rn(gy1, gy2), 0.5f);

    __shared__ int s_cand[27];
    int warp = threadIdx.x >> 5, lane = threadIdx.x & 31;

    if (warp < 3) {
        int start = (warp == 0) ? 0 : (warp == 1) ? 25600 : 32000;
        int len   = (warp == 0) ? 25600 : (warp == 1) ? 6400 : 1600;

        unsigned long long top[9];
#pragma unroll
        for (int j = 0; j < 9; j++) top[j] = ~0ull;

        for (int i = lane; i < len; i += 32) {
            int a = start + i;
            float4 ab = ((const float4*)anc)[a];
            float acx = __fmul_rn(__fadd_rn(ab.x, ab.z), 0.5f);
            float acy = __fmul_rn(__fadd_rn(ab.y, ab.w), 0.5f);
            float dx = __fsub_rn(gcx, acx), dy = __fsub_rn(gcy, acy);
            float d = __fsqrt_rn(__fadd_rn(__fmul_rn(dx, dx), __fmul_rn(dy, dy)));
            unsigned long long key =
                ((unsigned long long)__float_as_uint(d) << 32) | (unsigned)a;
            if (key < top[8]) {
                int j = 8;
                while (j > 0 && top[j - 1] > key) { top[j] = top[j - 1]; --j; }
                top[j] = key;
            }
        }
        // warp-merge: 9 rounds of global-min extraction (keys unique via index)
        int p = 0;
        for (int r = 0; r < 9; r++) {
            unsigned long long v = (p < 9) ? top[p] : ~0ull;
            unsigned long long m = v;
#pragma unroll
            for (int o = 16; o; o >>= 1) {
                unsigned long long t = __shfl_xor_sync(0xffffffffu, m, o);
                m = (t < m) ? t : m;
            }
            if (v == m) { s_cand[warp * 9 + r] = (int)(unsigned)(m & 0xffffffffull); p++; }
        }
    }
    __syncthreads();

    if (threadIdx.x < 32) {
        float ov = 0.f; int cand = 0; bool inside = false;
        if (lane < 27) {
            cand = s_cand[lane];
            float4 ab = ((const float4*)anc)[cand];
            ov = pair_iou(gx1, gy1, gx2, gy2, ab);
            float acx = __fmul_rn(__fadd_rn(ab.x, ab.z), 0.5f);
            float acy = __fmul_rn(__fadd_rn(ab.y, ab.w), 0.5f);
            float mn = fminf(fminf(__fsub_rn(acx, gx1), __fsub_rn(acy, gy1)),
                             fminf(__fsub_rn(gx2, acx), __fsub_rn(gy2, acy)));
            inside = mn > 1e-9f;
        }
        // mean over 27
        float s = ov;
#pragma unroll
        for (int o = 16; o; o >>= 1) s = __fadd_rn(s, __shfl_xor_sync(0xffffffffu, s, o));
        float mean = __fdiv_rn(s, 27.f);
        // std ddof=1
        float dv = (lane < 27) ? __fsub_rn(ov, mean) : 0.f;
        float d2 = __fmul_rn(dv, dv);
#pragma unroll
        for (int o = 16; o; o >>= 1) d2 = __fadd_rn(d2, __shfl_xor_sync(0xffffffffu, d2, o));
        float thr = __fadd_rn(mean, __fsqrt_rn(__fdiv_rn(d2, 26.f)));

        if (lane < 27 && inside && ov > thr) {
            atomicAdd(&g_cnt[b * NA + cand], 1);
            atomicMin(&g_first[b * NA + cand], g);
        }
    }
}

// ---------------- per-anchor resolve ----------------
__global__ void __launch_bounds__(256) k_resolve(const float* __restrict__ anc,
                                                 const float* __restrict__ gtb,
                                                 const float* __restrict__ gt_pro,
                                                 const float* __restrict__ gt_alp,
                                                 const float* __restrict__ gt_ads,
                                                 const float* __restrict__ pdb) {
    int idx = blockIdx.x * blockDim.x + threadIdx.x;
    if (idx >= BA) return;
    int b = idx / NA;
    int a = idx - b * NA;

    int cnt = g_cnt[idx];
    int tgt = 0, fg = 0;
    if (cnt == 1) {
        tgt = g_first[idx];
        fg = 1;
    } else if (cnt > 1) {
        // argmax over all 64 gts of pairwise IoU (first index on ties)
        float4 ab = ((const float4*)anc)[a];
        const float* gp = gtb + b * NMAX * 4;
        float best = -1.f; int bi = 0;
        for (int g = 0; g < NMAX; g++) {
            float ov = pair_iou(gp[4 * g], gp[4 * g + 1], gp[4 * g + 2], gp[4 * g + 3], ab);
            if (ov > best) { best = ov; bi = g; }
        }
        tgt = bi; fg = 1;
    }
    g_tgt[idx] = tgt;
    g_fgb[idx] = fg;

    float iou = 0.f;
    if (fg) {
        // _batched_iou(gt, pd): clipped areas, +1e-9 denom
        const float* gp = gtb + (b * NMAX + tgt) * 4;
        float4 pb = ((const float4*)pdb)[idx];
        float gx1 = gp[0], gy1 = gp[1], gx2 = gp[2], gy2 = gp[3];
        float a1 = __fmul_rn(fmaxf(__fsub_rn(gx2, gx1), 0.f), fmaxf(__fsub_rn(gy2, gy1), 0.f));
        float a2 = __fmul_rn(fmaxf(__fsub_rn(pb.z, pb.x), 0.f), fmaxf(__fsub_rn(pb.w, pb.y), 0.f));
        float iw = fmaxf(__fsub_rn(fminf(gx2, pb.z), fmaxf(gx1, pb.x)), 0.f);
        float ih = fmaxf(__fsub_rn(fminf(gy2, pb.w), fmaxf(gy1, pb.y)), 0.f);
        float ov = __fmul_rn(iw, ih);
        float den = __fadd_rn(__fsub_rn(__fadd_rn(a1, a2), ov), 1e-9f);
        iou = __fdiv_rn(ov, den);
    }
    g_iou[idx] = iou;

    int gi = b * NMAX + tgt;
    g_cls[idx]          = fg ? (int)gt_pro[gi] : NPRO_;
    g_cls[BA + idx]     = fg ? (int)gt_alp[gi] : NALP_;
    const float* ad = gt_ads + gi * 6;
#pragma unroll
    for (int j = 0; j < 6; j++)
        g_cls[(2 + j) * BA + idx] = fg ? (int)ad[j] : NADS_;
}

// ---------------- output fill (80.1M f32, write-bound) ----------------
// layout (units of BA): [0,8) int targets | [8,12) bboxes | [12,20) corners |
// [20,51) pro_scores | [51,75) alp_scores | [75,297) ads_scores | [297,298) fgb
__global__ void __launch_bounds__(256) k_fill(const float* __restrict__ gtb,
                                              const float* __restrict__ gtc,
                                              float* __restrict__ out) {
    unsigned i = blockIdx.x * blockDim.x + threadIdx.x;
    const unsigned BAu = BA;
    if (i >= 298u * BAu) return;

    float v;
    if (i < 8u * BAu) {
        v = (float)g_cls[i];
    } else if (i < 12u * BAu) {
        unsigned t = i - 8u * BAu;
        unsigned a = t >> 2, j = t & 3;
        unsigned b = a / NA;
        v = gtb[(b * NMAX + g_tgt[a]) * 4 + j];
    } else if (i < 20u * BAu) {
        unsigned t = i - 12u * BAu;
        unsigned a = t >> 3, j = t & 7;
        unsigned b = a / NA;
        v = gtc[(b * NMAX + g_tgt[a]) * 8 + j];
    } else if (i < 51u * BAu) {
        unsigned t = i - 20u * BAu;
        unsigned a = t / 31u, c = t - a * 31u;
        v = ((int)c == g_cls[a]) ? g_iou[a] : 0.f;
    } else if (i < 75u * BAu) {
        unsigned t = i - 51u * BAu;
        unsigned a = t / 24u, c = t - a * 24u;
        v = ((int)c == g_cls[BA + a]) ? g_iou[a] : 0.f;
    } else if (i < 297u * BAu) {
        unsigned t = i - 75u * BAu;
        unsigned s = t / (37u * BAu);
        unsigned t2 = t - s * (37u * BAu);
        unsigned a = t2 / 37u, c = t2 - a * 37u;
        v = ((int)c == g_cls[(2 + s) * BA + a]) ? g_iou[a] : 0.f;
    } else {
        unsigned r = i - 297u * BAu;
        v = g_fgb[r] ? 1.f : 0.f;
    }
    out[i] = v;
}

// ---------------- launch ----------------
extern "C" void kernel_launch(void* const* d_in, const int* in_sizes, int n_in,
                              void* d_out, int out_size) {
    const float *anc = nullptr, *pd = nullptr, *gtb = nullptr, *gtc = nullptr,
                *ads = nullptr, *pro = nullptr, *alp = nullptr, *msk = nullptr;
    int n512 = 0;
    for (int i = 0; i < n_in; i++) {
        int s = in_sizes[i];
        const float* p = (const float*)d_in[i];
        if      (s == 134400)  anc = p;       // anc_bboxes [33600,4]
        else if (s == 1075200) pd  = p;       // pd_bboxes  [8,33600,4]
        else if (s == 2048)    gtb = p;       // gt_bboxes  [8,64,4]
        else if (s == 4096)    gtc = p;       // gt_corners [8,64,8]
        else if (s == 3072)    ads = p;       // gt_ads     [8,64,6]
        else if (s == 512) {                  // gt_pro, gt_alp, mask_gt (in order)
            if (n512 == 0)      pro = p;
            else if (n512 == 1) alp = p;
            else                msk = p;
            n512++;
        }
    }
    float* out = (float*)d_out;

    k_init<<<(BA + 255) / 256, 256>>>();
    k_assign<<<BSZ * NMAX, 96>>>(anc, gtb, msk);
    k_resolve<<<(BA + 255) / 256, 256>>>(anc, gtb, pro, alp, ads, pd);

    unsigned total = 298u * BA;                 // 80,102,400 elements
    k_fill<<<(total + 255) / 256, 256>>>(gtb, gtc, out);
}

// round 2
// speedup vs baseline: 3.0226x; 3.0226x over previous
#include <cuda_runtime.h>

#define BSZ   8
#define NMAX  64
#define NA    33600
#define BA    (BSZ * NA)          // 268800
#define NPRO_ 31
#define NALP_ 24
#define NADS_ 37

// ---------------- scratch (device globals; no allocation) ----------------
__device__ int    g_cnt[BA];
__device__ int    g_first[BA];
__device__ int    g_tgt[BA];
__device__ int    g_fgb[BA];
__device__ float  g_iou[BA];
__device__ int    g_cls[8 * BA];   // j*BA + a : j=0 pro, 1 alp, 2..7 ads
__device__ float2 g_ctr[NA];       // anchor centers

// ---------------- init / prep ----------------
__global__ void k_init(const float* __restrict__ anc) {
    int i = blockIdx.x * blockDim.x + threadIdx.x;
    if (i < BA) { g_cnt[i] = 0; g_first[i] = 0x7fffffff; }
    if (i < NA) {
        float4 ab = ((const float4*)anc)[i];
        g_ctr[i] = make_float2(__fmul_rn(__fadd_rn(ab.x, ab.z), 0.5f),
                               __fmul_rn(__fadd_rn(ab.y, ab.w), 0.5f));
    }
}

// pairwise IoU exactly as reference _pairwise_iou (union clamp 1e-6)
__device__ __forceinline__ float pair_iou(float gx1, float gy1, float gx2, float gy2,
                                          float4 ab) {
    float ga  = __fmul_rn(__fsub_rn(gx2, gx1), __fsub_rn(gy2, gy1));
    float aa  = __fmul_rn(__fsub_rn(ab.z, ab.x), __fsub_rn(ab.w, ab.y));
    float iw  = fmaxf(__fsub_rn(fminf(gx2, ab.z), fmaxf(gx1, ab.x)), 0.f);
    float ih  = fmaxf(__fsub_rn(fminf(gy2, ab.w), fmaxf(gy1, ab.y)), 0.f);
    float ovl = __fmul_rn(iw, ih);
    float uni = fmaxf(__fsub_rn(__fadd_rn(ga, aa), ovl), 1e-6f);
    return __fdiv_rn(ovl, uni);
}

// ---------------- per-GT: top-9/level candidates, threshold, positives ----
// 9 warps: w0-5 -> level0 (25600), w6-7 -> level1 (6400), w8 -> level2 (1600)
__global__ void __launch_bounds__(288) k_assign(const float* __restrict__ anc,
                                                const float* __restrict__ gtb,
                                                const float* __restrict__ mask_gt) {
    int bg = blockIdx.x;                 // b*64 + g
    if (mask_gt[bg] <= 0.f) return;
    int b = bg >> 6;
    int g = bg & 63;

    const float* gt = gtb + bg * 4;
    float gx1 = gt[0], gy1 = gt[1], gx2 = gt[2], gy2 = gt[3];
    float gcx = __fmul_rn(__fadd_rn(gx1, gx2), 0.5f);
    float gcy = __fmul_rn(__fadd_rn(gy1, gy2), 0.5f);

    __shared__ unsigned long long s_keys[81];   // 9 warps x 9
    __shared__ int s_cand[27];

    int w = threadIdx.x >> 5, lane = threadIdx.x & 31;

    int astart, len, glane, gsize;
    if (w < 6)      { astart = 0;     len = 25600; glane = w * 32 + lane;       gsize = 192; }
    else if (w < 8) { astart = 25600; len = 6400;  glane = (w - 6) * 32 + lane; gsize = 64;  }
    else            { astart = 32000; len = 1600;  glane = lane;                gsize = 32;  }

    unsigned long long top[9];
#pragma unroll
    for (int j = 0; j < 9; j++) top[j] = ~0ull;

#pragma unroll 4
    for (int i = glane; i < len; i += gsize) {
        int a = astart + i;
        float2 c = g_ctr[a];
        float dx = __fsub_rn(gcx, c.x), dy = __fsub_rn(gcy, c.y);
        float d = __fsqrt_rn(__fadd_rn(__fmul_rn(dx, dx), __fmul_rn(dy, dy)));
        unsigned long long key =
            ((unsigned long long)__float_as_uint(d) << 32) | (unsigned)a;
        if (key < top[8]) {
            int j = 8;
            while (j > 0 && top[j - 1] > key) { top[j] = top[j - 1]; --j; }
            top[j] = key;
        }
    }

    // per-warp top-9 extraction (keys unique via embedded index)
    {
        int p = 0;
        for (int r = 0; r < 9; r++) {
            unsigned long long v = (p < 9) ? top[p] : ~0ull;
            unsigned long long m = v;
#pragma unroll
            for (int o = 16; o; o >>= 1) {
                unsigned long long t = __shfl_xor_sync(0xffffffffu, m, o);
                m = (t < m) ? t : m;
            }
            if (v == m) { s_keys[w * 9 + r] = m; p++; }
        }
    }
    __syncthreads();

    // per-level merge (3 serial threads; 54/18/9 keys)
    if (threadIdx.x < 3) {
        int tid = threadIdx.x;
        int nw = (tid == 0) ? 6 : (tid == 1) ? 2 : 1;
        int bw = (tid == 0) ? 0 : (tid == 1) ? 6 : 8;
        unsigned long long mtop[9];
#pragma unroll
        for (int j = 0; j < 9; j++) mtop[j] = ~0ull;
        for (int w2 = 0; w2 < nw; w2++) {
#pragma unroll
            for (int r = 0; r < 9; r++) {
                unsigned long long k = s_keys[(bw + w2) * 9 + r];
                if (k < mtop[8]) {
                    int j = 8;
                    while (j > 0 && mtop[j - 1] > k) { mtop[j] = mtop[j - 1]; --j; }
                    mtop[j] = k;
                }
            }
        }
#pragma unroll
        for (int r = 0; r < 9; r++)
            s_cand[tid * 9 + r] = (int)(unsigned)(mtop[r] & 0xffffffffull);
    }
    __syncthreads();

    // final stage: threshold over 27 candidates + positivity scatter
    if (threadIdx.x < 32) {
        float ov = 0.f; int cand = 0; bool inside = false;
        if (lane < 27) {
            cand = s_cand[lane];
            float4 ab = ((const float4*)anc)[cand];
            ov = pair_iou(gx1, gy1, gx2, gy2, ab);
            float acx = __fmul_rn(__fadd_rn(ab.x, ab.z), 0.5f);
            float acy = __fmul_rn(__fadd_rn(ab.y, ab.w), 0.5f);
            float mn = fminf(fminf(__fsub_rn(acx, gx1), __fsub_rn(acy, gy1)),
                             fminf(__fsub_rn(gx2, acx), __fsub_rn(gy2, acy)));
            inside = mn > 1e-9f;
        }
        float s = ov;
#pragma unroll
        for (int o = 16; o; o >>= 1) s = __fadd_rn(s, __shfl_xor_sync(0xffffffffu, s, o));
        float mean = __fdiv_rn(s, 27.f);
        float dv = (lane < 27) ? __fsub_rn(ov, mean) : 0.f;
        float d2 = __fmul_rn(dv, dv);
#pragma unroll
        for (int o = 16; o; o >>= 1) d2 = __fadd_rn(d2, __shfl_xor_sync(0xffffffffu, d2, o));
        float thr = __fadd_rn(mean, __fsqrt_rn(__fdiv_rn(d2, 26.f)));

        if (lane < 27 && inside && ov > thr) {
            atomicAdd(&g_cnt[b * NA + cand], 1);
            atomicMin(&g_first[b * NA + cand], g);
        }
    }
}

// ---------------- per-anchor resolve ----------------
__global__ void __launch_bounds__(256) k_resolve(const float* __restrict__ anc,
                                                 const float* __restrict__ gtb,
                                                 const float* __restrict__ gt_pro,
                                                 const float* __restrict__ gt_alp,
                                                 const float* __restrict__ gt_ads,
                                                 const float* __restrict__ pdb) {
    int idx = blockIdx.x * blockDim.x + threadIdx.x;
    if (idx >= BA) return;
    int b = idx / NA;
    int a = idx - b * NA;

    int cnt = g_cnt[idx];
    int tgt = 0, fg = 0;
    if (cnt == 1) {
        tgt = g_first[idx];
        fg = 1;
    } else if (cnt > 1) {
        // argmax over all 64 gts of pairwise IoU (first index on ties)
        float4 ab = ((const float4*)anc)[a];
        const float* gp = gtb + b * NMAX * 4;
        float best = -1.f; int bi = 0;
        for (int g = 0; g < NMAX; g++) {
            float ov = pair_iou(gp[4 * g], gp[4 * g + 1], gp[4 * g + 2], gp[4 * g + 3], ab);
            if (ov > best) { best = ov; bi = g; }
        }
        tgt = bi; fg = 1;
    }
    g_tgt[idx] = tgt;
    g_fgb[idx] = fg;

    float iou = 0.f;
    if (fg) {
        const float* gp = gtb + (b * NMAX + tgt) * 4;
        float4 pb = ((const float4*)pdb)[idx];
        float gx1 = gp[0], gy1 = gp[1], gx2 = gp[2], gy2 = gp[3];
        float a1 = __fmul_rn(fmaxf(__fsub_rn(gx2, gx1), 0.f), fmaxf(__fsub_rn(gy2, gy1), 0.f));
        float a2 = __fmul_rn(fmaxf(__fsub_rn(pb.z, pb.x), 0.f), fmaxf(__fsub_rn(pb.w, pb.y), 0.f));
        float iw = fmaxf(__fsub_rn(fminf(gx2, pb.z), fmaxf(gx1, pb.x)), 0.f);
        float ih = fmaxf(__fsub_rn(fminf(gy2, pb.w), fmaxf(gy1, pb.y)), 0.f);
        float ov = __fmul_rn(iw, ih);
        float den = __fadd_rn(__fsub_rn(__fadd_rn(a1, a2), ov), 1e-9f);
        iou = __fdiv_rn(ov, den);
    }
    g_iou[idx] = iou;

    int gi = b * NMAX + tgt;
    g_cls[idx]          = fg ? (int)gt_pro[gi] : NPRO_;
    g_cls[BA + idx]     = fg ? (int)gt_alp[gi] : NALP_;
    const float* ad = gt_ads + gi * 6;
#pragma unroll
    for (int j = 0; j < 6; j++)
        g_cls[(2 + j) * BA + idx] = fg ? (int)ad[j] : NADS_;
}

// ---------------- output fill: 1 float4 store per thread ----------------
// layout (units of BA): [0,8) int targets | [8,12) bboxes | [12,20) corners |
// [20,51) pro | [51,75) alp | [75,297) ads(6x37) | [297,298) fgb
__global__ void __launch_bounds__(256) k_fill(const float* __restrict__ gtb,
                                              const float* __restrict__ gtc,
                                              float4* __restrict__ out4) {
    const unsigned BAu = BA;
    const unsigned NQ = (298u * BAu) >> 2;
    unsigned q = blockIdx.x * blockDim.x + threadIdx.x;
    if (q >= NQ) return;
    unsigned i = q << 2;

    float4 v;
    if (i < 8u * BAu) {
        int4 c = ((const int4*)g_cls)[q];
        v = make_float4((float)c.x, (float)c.y, (float)c.z, (float)c.w);
    } else if (i < 12u * BAu) {
        unsigned a = (i - 8u * BAu) >> 2;
        unsigned b = a / NA;
        v = ((const float4*)gtb)[b * NMAX + g_tgt[a]];
    } else if (i < 20u * BAu) {
        unsigned t = i - 12u * BAu;
        unsigned a = t >> 3, half = (t >> 2) & 1;
        unsigned b = a / NA;
        v = ((const float4*)gtc)[(b * NMAX + g_tgt[a]) * 2 + half];
    } else if (i < 51u * BAu) {
        unsigned t = i - 20u * BAu;
        unsigned a0 = t / 31u, c0 = t - a0 * 31u;
        int cls0 = g_cls[a0]; float iou0 = g_iou[a0];
        int cls1 = cls0; float iou1 = iou0;
        if (c0 >= 28u) { cls1 = g_cls[a0 + 1]; iou1 = g_iou[a0 + 1]; }
        float r[4];
#pragma unroll
        for (int j = 0; j < 4; j++) {
            unsigned c = c0 + j; bool wr = c >= 31u; if (wr) c -= 31u;
            r[j] = ((int)c == (wr ? cls1 : cls0)) ? (wr ? iou1 : iou0) : 0.f;
        }
        v = make_float4(r[0], r[1], r[2], r[3]);
    } else if (i < 75u * BAu) {
        unsigned t = i - 51u * BAu;
        unsigned a = t / 24u, c0 = t - a * 24u;     // c0 multiple of 4 -> no wrap
        int cls = g_cls[BA + a]; float iou = g_iou[a];
        float r[4];
#pragma unroll
        for (int j = 0; j < 4; j++)
            r[j] = ((int)(c0 + j) == cls) ? iou : 0.f;
        v = make_float4(r[0], r[1], r[2], r[3]);
    } else if (i < 297u * BAu) {
        unsigned t = i - 75u * BAu;
        unsigned s = t / (37u * BAu);
        unsigned t2 = t - s * (37u * BAu);
        unsigned a0 = t2 / 37u, c0 = t2 - a0 * 37u;
        int cls0 = g_cls[(2 + s) * BA + a0]; float iou0 = g_iou[a0];
        int cls1 = cls0; float iou1 = iou0;
        if (c0 >= 34u) { cls1 = g_cls[(2 + s) * BA + a0 + 1]; iou1 = g_iou[a0 + 1]; }
        float r[4];
#pragma unroll
        for (int j = 0; j < 4; j++) {
            unsigned c = c0 + j; bool wr = c >= 37u; if (wr) c -= 37u;
            r[j] = ((int)c == (wr ? cls1 : cls0)) ? (wr ? iou1 : iou0) : 0.f;
        }
        v = make_float4(r[0], r[1], r[2], r[3]);
    } else {
        unsigned r0 = (i - 297u * BAu) >> 2;
        int4 f = ((const int4*)g_fgb)[r0];
        v = make_float4(f.x ? 1.f : 0.f, f.y ? 1.f : 0.f,
                        f.z ? 1.f : 0.f, f.w ? 1.f : 0.f);
    }
    out4[q] = v;
}

// ---------------- launch ----------------
extern "C" void kernel_launch(void* const* d_in, const int* in_sizes, int n_in,
                              void* d_out, int out_size) {
    const float *anc = nullptr, *pd = nullptr, *gtb = nullptr, *gtc = nullptr,
                *ads = nullptr, *pro = nullptr, *alp = nullptr, *msk = nullptr;
    int n512 = 0;
    for (int i = 0; i < n_in; i++) {
        int s = in_sizes[i];
        const float* p = (const float*)d_in[i];
        if      (s == 134400)  anc = p;       // anc_bboxes [33600,4]
        else if (s == 1075200) pd  = p;       // pd_bboxes  [8,33600,4]
        else if (s == 2048)    gtb = p;       // gt_bboxes  [8,64,4]
        else if (s == 4096)    gtc = p;       // gt_corners [8,64,8]
        else if (s == 3072)    ads = p;       // gt_ads     [8,64,6]
        else if (s == 512) {                  // gt_pro, gt_alp, mask_gt (in order)
            if (n512 == 0)      pro = p;
            else if (n512 == 1) alp = p;
            else                msk = p;
            n512++;
        }
    }
    float4* out4 = (float4*)d_out;

    k_init<<<(BA + 255) / 256, 256>>>(anc);
    k_assign<<<BSZ * NMAX, 288>>>(anc, gtb, msk);
    k_resolve<<<(BA + 255) / 256, 256>>>(anc, gtb, pro, alp, ads, pd);

    unsigned nq = (298u * BA) >> 2;            // 20,025,600 quads
    k_fill<<<(nq + 255) / 256, 256>>>(gtb, gtc, out4);
}

// round 3
// speedup vs baseline: 6.9612x; 2.3031x over previous
#include <cuda_runtime.h>

#define BSZ   8
#define NMAX  64
#define NA    33600
#define BA    (BSZ * NA)          // 268800
#define NPRO_ 31
#define NALP_ 24
#define NADS_ 37

// ---------------- scratch (device globals; no allocation) ----------------
__device__ int    g_cnt[BA];
__device__ int    g_first[BA];
__device__ float2 g_ctr[NA];       // anchor centers (same formula as reference)

// ---------------- init / prep ----------------
__global__ void k_init(const float* __restrict__ anc) {
    int i = blockIdx.x * blockDim.x + threadIdx.x;
    if (i < BA) { g_cnt[i] = 0; g_first[i] = 0x7fffffff; }
    if (i < NA) {
        float4 ab = ((const float4*)anc)[i];
        g_ctr[i] = make_float2(__fmul_rn(__fadd_rn(ab.x, ab.z), 0.5f),
                               __fmul_rn(__fadd_rn(ab.y, ab.w), 0.5f));
    }
}

// pairwise IoU exactly as reference _pairwise_iou (union clamp 1e-6)
__device__ __forceinline__ float pair_iou(float gx1, float gy1, float gx2, float gy2,
                                          float4 ab) {
    float ga  = __fmul_rn(__fsub_rn(gx2, gx1), __fsub_rn(gy2, gy1));
    float aa  = __fmul_rn(__fsub_rn(ab.z, ab.x), __fsub_rn(ab.w, ab.y));
    float iw  = fmaxf(__fsub_rn(fminf(gx2, ab.z), fmaxf(gx1, ab.x)), 0.f);
    float ih  = fmaxf(__fsub_rn(fminf(gy2, ab.w), fmaxf(gy1, ab.y)), 0.f);
    float ovl = __fmul_rn(iw, ih);
    float uni = fmaxf(__fsub_rn(__fadd_rn(ga, aa), ovl), 1e-6f);
    return __fdiv_rn(ovl, uni);
}

// ---------------- per-GT assign: analytic 6x6 window per level -----------
// Anchors form a uniform grid per level. The 9 nearest grid points to any
// query lie within 2.1213 cell units; everything outside the 6x6 index
// window [floor(u)-2, floor(u)+3] is >= 2.99 units away. So exact top-9
// (including the (dist_bits, index) tie-break that matches jax.lax.top_k)
// needs only 36 candidates per level.
__global__ void __launch_bounds__(32) k_assign(const float* __restrict__ anc,
                                               const float* __restrict__ gtb,
                                               const float* __restrict__ mask_gt) {
    int bg = blockIdx.x;                 // b*64 + g
    if (mask_gt[bg] <= 0.f) return;
    int b = bg >> 6;
    int g = bg & 63;

    const float* gt = gtb + bg * 4;
    float gx1 = gt[0], gy1 = gt[1], gx2 = gt[2], gy2 = gt[3];
    float gcx = __fmul_rn(__fadd_rn(gx1, gx2), 0.5f);
    float gcy = __fmul_rn(__fadd_rn(gy1, gy2), 0.5f);

    __shared__ int s_cand[27];
    int lane = threadIdx.x;

    if (lane < 3) {
        int   n     = (lane == 0) ? 160 : (lane == 1) ? 80 : 40;
        int   start = (lane == 0) ? 0   : (lane == 1) ? 25600 : 32000;
        float inv   = (lane == 0) ? 0.125f : (lane == 1) ? 0.0625f : 0.03125f;

        int ix0 = (int)floorf(gcx * inv - 0.5f) - 2;
        int iy0 = (int)floorf(gcy * inv - 0.5f) - 2;
        ix0 = min(max(ix0, 0), n - 6);
        iy0 = min(max(iy0, 0), n - 6);

        unsigned long long top[9];
#pragma unroll
        for (int j = 0; j < 9; j++) top[j] = ~0ull;

#pragma unroll
        for (int dy = 0; dy < 6; dy++) {
            int rowbase = start + (iy0 + dy) * n + ix0;
#pragma unroll
            for (int dx = 0; dx < 6; dx++) {
                int a = rowbase + dx;
                float2 c = g_ctr[a];
                float ddx = __fsub_rn(gcx, c.x), ddy = __fsub_rn(gcy, c.y);
                float d = __fsqrt_rn(__fadd_rn(__fmul_rn(ddx, ddx),
                                               __fmul_rn(ddy, ddy)));
                unsigned long long key =
                    ((unsigned long long)__float_as_uint(d) << 32) | (unsigned)a;
                if (key < top[8]) {
                    top[8] = key;
#pragma unroll
                    for (int j = 8; j > 0; --j) {
                        unsigned long long lo = top[j-1] < top[j] ? top[j-1] : top[j];
                        unsigned long long hi = top[j-1] < top[j] ? top[j]   : top[j-1];
                        top[j-1] = lo; top[j] = hi;
                    }
                }
            }
        }
#pragma unroll
        for (int r = 0; r < 9; r++)
            s_cand[lane * 9 + r] = (int)(unsigned)(top[r] & 0xffffffffull);
    }
    __syncwarp();

    // threshold over 27 candidates + positivity scatter (bit-exact reductions)
    {
        float ov = 0.f; int cand = 0; bool inside = false;
        if (lane < 27) {
            cand = s_cand[lane];
            float4 ab = ((const float4*)anc)[cand];
            ov = pair_iou(gx1, gy1, gx2, gy2, ab);
            float acx = __fmul_rn(__fadd_rn(ab.x, ab.z), 0.5f);
            float acy = __fmul_rn(__fadd_rn(ab.y, ab.w), 0.5f);
            float mn = fminf(fminf(__fsub_rn(acx, gx1), __fsub_rn(acy, gy1)),
                             fminf(__fsub_rn(gx2, acx), __fsub_rn(gy2, acy)));
            inside = mn > 1e-9f;
        }
        float s = ov;
#pragma unroll
        for (int o = 16; o; o >>= 1) s = __fadd_rn(s, __shfl_xor_sync(0xffffffffu, s, o));
        float mean = __fdiv_rn(s, 27.f);
        float dv = (lane < 27) ? __fsub_rn(ov, mean) : 0.f;
        float d2 = __fmul_rn(dv, dv);
#pragma unroll
        for (int o = 16; o; o >>= 1) d2 = __fadd_rn(d2, __shfl_xor_sync(0xffffffffu, d2, o));
        float thr = __fadd_rn(mean, __fsqrt_rn(__fdiv_rn(d2, 26.f)));

        if (lane < 27 && inside && ov > thr) {
            atomicAdd(&g_cnt[b * NA + cand], 1);
            atomicMin(&g_first[b * NA + cand], g);
        }
    }
}

// ---------------- zero-fill score region [20BA, 297BA) -------------------
__global__ void __launch_bounds__(256) k_zero(float4* __restrict__ p, unsigned nq) {
    unsigned i = blockIdx.x * blockDim.x + threadIdx.x;
    if (i < nq) p[i] = make_float4(0.f, 0.f, 0.f, 0.f);
}

// ---------------- per-anchor resolve + ALL dense output writes -----------
// out layout (units of BA floats): [0,8) int targets | [8,12) bboxes |
// [12,20) corners | [20,51) pro | [51,75) alp | [75,297) ads | [297,298) fgb
__global__ void __launch_bounds__(256) k_resolve(const float* __restrict__ anc,
                                                 const float* __restrict__ gtb,
                                                 const float* __restrict__ gtc,
                                                 const float* __restrict__ gt_pro,
                                                 const float* __restrict__ gt_alp,
                                                 const float* __restrict__ gt_ads,
                                                 const float* __restrict__ pdb,
                                                 float* __restrict__ out) {
    int idx = blockIdx.x * blockDim.x + threadIdx.x;
    if (idx >= BA) return;
    int b = idx / NA;
    int a = idx - b * NA;
    const unsigned BAu = BA;

    int cnt = g_cnt[idx];
    int tgt = 0, fg = 0;
    if (cnt == 1) {
        tgt = g_first[idx];
        fg = 1;
    } else if (cnt > 1) {
        // argmax over all 64 gts of pairwise IoU (first index on ties)
        float4 ab = ((const float4*)anc)[a];
        const float* gp = gtb + b * NMAX * 4;
        float best = -1.f; int bi = 0;
        for (int g = 0; g < NMAX; g++) {
            float ov = pair_iou(gp[4*g], gp[4*g+1], gp[4*g+2], gp[4*g+3], ab);
            if (ov > best) { best = ov; bi = g; }
        }
        tgt = bi; fg = 1;
    }

    float iou = 0.f;
    if (fg) {
        // _batched_iou(gt, pd): clipped areas, +1e-9 denom
        const float* gp = gtb + (b * NMAX + tgt) * 4;
        float4 pb = ((const float4*)pdb)[idx];
        float gx1 = gp[0], gy1 = gp[1], gx2 = gp[2], gy2 = gp[3];
        float a1 = __fmul_rn(fmaxf(__fsub_rn(gx2, gx1), 0.f), fmaxf(__fsub_rn(gy2, gy1), 0.f));
        float a2 = __fmul_rn(fmaxf(__fsub_rn(pb.z, pb.x), 0.f), fmaxf(__fsub_rn(pb.w, pb.y), 0.f));
        float iw = fmaxf(__fsub_rn(fminf(gx2, pb.z), fmaxf(gx1, pb.x)), 0.f);
        float ih = fmaxf(__fsub_rn(fminf(gy2, pb.w), fmaxf(gy1, pb.y)), 0.f);
        float ov = __fmul_rn(iw, ih);
        float den = __fadd_rn(__fsub_rn(__fadd_rn(a1, a2), ov), 1e-9f);
        iou = __fdiv_rn(ov, den);
    }

    int gi = b * NMAX + tgt;

    // int-class targets (stored as exact small-int floats)
    int cpro = fg ? (int)gt_pro[gi] : NPRO_;
    int calp = fg ? (int)gt_alp[gi] : NALP_;
    out[idx]       = (float)cpro;
    out[BAu + idx] = (float)calp;
    const float* ad = gt_ads + gi * 6;
    int cads[6];
#pragma unroll
    for (int j = 0; j < 6; j++) {
        cads[j] = fg ? (int)ad[j] : NADS_;
        out[(2 + j) * BAu + idx] = (float)cads[j];
    }

    // bboxes + corners (gathered, vector stores)
    ((float4*)(out + 8u * BAu))[idx] = ((const float4*)gtb)[gi];
    ((float4*)(out + 12u * BAu))[idx * 2]     = ((const float4*)gtc)[gi * 2];
    ((float4*)(out + 12u * BAu))[idx * 2 + 1] = ((const float4*)gtc)[gi * 2 + 1];

    // fgb
    out[297u * BAu + idx] = fg ? 1.f : 0.f;

    // sparse one-hot score scatter (score region pre-zeroed by k_zero)
    if (fg) {
        out[20u * BAu + (unsigned)idx * 31u + cpro] = iou;
        out[51u * BAu + (unsigned)idx * 24u + calp] = iou;
#pragma unroll
        for (int j = 0; j < 6; j++)
            out[(75u + j * 37u) * BAu + (unsigned)idx * 37u + cads[j]] = iou;
    }
}

// ---------------- launch ----------------
extern "C" void kernel_launch(void* const* d_in, const int* in_sizes, int n_in,
                              void* d_out, int out_size) {
    const float *anc = nullptr, *pd = nullptr, *gtb = nullptr, *gtc = nullptr,
                *ads = nullptr, *pro = nullptr, *alp = nullptr, *msk = nullptr;
    int n512 = 0;
    for (int i = 0; i < n_in; i++) {
        int s = in_sizes[i];
        const float* p = (const float*)d_in[i];
        if      (s == 134400)  anc = p;       // anc_bboxes [33600,4]
        else if (s == 1075200) pd  = p;       // pd_bboxes  [8,33600,4]
        else if (s == 2048)    gtb = p;       // gt_bboxes  [8,64,4]
        else if (s == 4096)    gtc = p;       // gt_corners [8,64,8]
        else if (s == 3072)    ads = p;       // gt_ads     [8,64,6]
        else if (s == 512) {                  // gt_pro, gt_alp, mask_gt (in order)
            if (n512 == 0)      pro = p;
            else if (n512 == 1) alp = p;
            else                msk = p;
            n512++;
        }
    }
    float* out = (float*)d_out;

    k_init<<<(BA + 255) / 256, 256>>>(anc);
    k_assign<<<BSZ * NMAX, 32>>>(anc, gtb, msk);

    // zero the one-hot score region [20BA, 297BA)
    unsigned nq = (277u * BA) >> 2;            // 18,614,400 float4s
    k_zero<<<(nq + 255) / 256, 256>>>((float4*)(out + 20u * (unsigned)BA), nq);

    k_resolve<<<(BA + 255) / 256, 256>>>(anc, gtb, gtc, pro, alp, ads, pd, out);
}